// round 17
// baseline (speedup 1.0000x reference)
#include <cuda_runtime.h>

#define D_DIM 2048
#define TPB   256
#define EPT   8      // 256*8 = 2048 = one row per block-iteration
#define PGRID 1216   // persistent grid: 152 SMs * 8 CTAs

__global__ __launch_bounds__(TPB, 6)
void mxint_softmax_kernel(const float* __restrict__ x, float* __restrict__ out,
                          int nrows)
{
    const int tid  = threadIdx.x;
    const int lane = tid & 31;
    const int warp = tid >> 5;

    __shared__ int   s_acc[48];      // buckets [16..31] (e'+16), zero aprons both sides
    __shared__ int   s_warpmax[8];
    __shared__ int   s_ms7[32];      // per-idx packed (s7<<8)|mu
    __shared__ float s_res[512];     // final result keyed by pe

    // Per-lane LUT register (hoisted; amortized over ~7 rows):
    // lut[lane] = clip(rne(2^(lane/32) * 64), 127).  exp2f err (~2 ulp) is
    // ~1000x below min distance (0.0097) to any .5 boundary.
    int lutreg  = min(127, (int)rintf(exp2f(fmaf((float)lane, 0.03125f, 6.0f))));
    int lutreg4 = lutreg << 4;       // mexp*16 for the bucket sum

    const float MAGIC = 12582912.0f;         // 1.5 * 2^23
    const int   grid  = gridDim.x;

    int row = blockIdx.x;
    const float* xr = x + (size_t)row * D_DIM + tid * EPT;
    float4 a0 = *(const float4*)(xr);
    float4 a1 = *(const float4*)(xr + 4);

    for (;;) {
        // ---- Prefetch next row BEFORE any compute on this row (uniform
        // branch; ~2000 cyc of work below hides the ~600 cyc DRAM latency).
        int  nrow = row + grid;
        bool more = nrow < nrows;
        float4 b0, b1;
        if (more) {
            const float* xn = x + (size_t)nrow * D_DIM + tid * EPT;
            b0 = *(const float4*)(xn);
            b1 = *(const float4*)(xn + 4);
        }

        if (tid < 48) s_acc[tid] = 0;    // safe: prior bar4 dominates all readers

        float xs[EPT] = {a0.x, a0.y, a0.z, a0.w, a1.x, a1.y, a1.z, a1.w};

        int   pe8[EPT];
        float yf[EPT];

        #pragma unroll
        for (int k = 0; k < EPT; k++) {
            float xv = xs[k];
            int bits = __float_as_int(xv);
            // u = biased exp of e1 = ceil(log2|x|): (2*abits-2)>>24 ==
            // (abits-1)>>23 (unsigned; sign falls off the left shift). Clamp
            // makes e1 >= -8 (abits=0 -> u=254, harmless: m1f==0 -> pe=256).
            // The float32 log2 rounding quirk (m23 in {1,2}) provably never
            // changes t (both variants saturate / floor identically).
            int u = max((int)((((unsigned)bits << 1) - 2u) >> 24), 118);
            // m1 = clip(rne(x * 2^(7-e1)), -128, 127) via magic-constant rne
            // (exact incl. ties-to-even: |x*2^(7-e1)| <= 128 << 2^22, C even).
            float s = __int_as_float((int)(0x82000000u - ((unsigned)u << 23)));
            float m1f = fmaf(xv, s, MAGIC) - MAGIC;
            m1f = fminf(m1f, 127.0f);        // 128 only at exact +pow2: clip
            // pe = clip(floor(m1*46*2^(e1-7)) + 256, 0, 511); +256 folded into
            // the fma (exact: 13-bit int * pow2, ulp >= 2^-15, |sum| < 512).
            // Upper clamp in float (fma pipe); lower clamp free via
            // F2I.U32.RD negative saturation.  Input has no NaN/inf.
            float c2 = __int_as_float((int)(((unsigned)u << 23) + 0xFFB80000u));
            float y  = fminf(fmaf(m1f, c2, 256.0f), 511.0f);
            yf[k]    = y;
            pe8[k]   = (int)__float2uint_rd(y);  // pe = (e+8)*32 + idx
        }
        // Running max in float (FMNMX tree, fma pipe; F2I.RD monotone so
        // converting the max equals max of the conversions).
        float rf = fmaxf(fmaxf(fmaxf(yf[0], yf[1]), fmaxf(yf[2], yf[3])),
                         fmaxf(fmaxf(yf[4], yf[5]), fmaxf(yf[6], yf[7])));
        int run = (int)__float2uint_rd(rf);

        // Block-wide inclusive prefix max of pe over thread order (pe lex
        // (e,idx), so (prefix-max pe)>>5 == prefix-max of e').
        int inc = run;
        #pragma unroll
        for (int o = 1; o < 32; o <<= 1) {
            int v = __shfl_up_sync(0xffffffffu, inc, o);
            if (lane >= o) inc = max(inc, v);
        }
        int excl = __shfl_up_sync(0xffffffffu, inc, 1);
        if (lane == 0) excl = 0;
        if (lane == 31) s_warpmax[warp] = inc;
        __syncthreads();                     // bar1 (orders s_acc init too)

        // Cross-warp base / block max via REDUX (conflict-free LDS).
        int wm     = s_warpmax[lane & 7];
        int bmaxpe = __reduce_max_sync(0xffffffffu, wm);
        int basew  = __reduce_max_sync(0xffffffffu, ((lane & 7) < warp) ? wm : 0);
        int base   = max(excl, basew);

        // Bucket by plateau value E (prefix max of e'). Bit-exact vs the
        // sequential scan: within a plateau adds are exact per-element
        // floors; cross-plateau shifts compose.  Fast path: if a lane's
        // prefix base dominates all its elements, plateau is constant.
        bool fastp = ((base >> 5) >= (run >> 5));
        if (__ballot_sync(0xffffffffu, fastp) == 0xffffffffu) {
            const int E = base >> 5;         // per-lane constant plateau
            int acc = 0;
            #pragma unroll
            for (int k = 0; k < EPT; k++) {
                int pe = pe8[k];
                // me16 >> (E-e') == (me16 << e') >> E  (me16<<15 < 2^26)
                int ms = __shfl_sync(0xffffffffu, lutreg4, pe);  // srcLane mod 32
                acc += (ms << (pe >> 5)) >> E;
            }
            // Warp-aggregate when E is warp-uniform (common): 1 ATOMS
            // instead of 32 same-address ATOMS.
            int E0 = __shfl_sync(0xffffffffu, E, 0);
            if (__all_sync(0xffffffffu, E == E0)) {
                int sred = __reduce_add_sync(0xffffffffu, acc);
                if (lane == 0) atomicAdd(&s_acc[E0 + 16], sred);
            } else {
                atomicAdd(&s_acc[E + 16], acc);
            }
        } else {
            int run2 = base, curE = -1, acc = 0;
            #pragma unroll
            for (int k = 0; k < EPT; k++) {
                int pe = pe8[k];
                run2 = max(run2, pe);
                int Ee = run2 >> 5;
                int ms = __shfl_sync(0xffffffffu, lutreg4, pe);
                int c  = (ms << (pe >> 5)) >> Ee;
                if (Ee != curE) {
                    if (k) atomicAdd(&s_acc[curE + 16], acc);
                    curE = Ee; acc = 0;
                }
                acc += c;
            }
            atomicAdd(&s_acc[curE + 16], acc);
        }
        __syncthreads();                     // bar2

        // Warp 0 only.  The 16-step serial combine equals its closed form
        // accv = (Sum_k bp[k] << k) >> 15 (halving-floor recurrence composes
        // to one floor) — DATA-PARALLEL: lane l<16 loads one bucket, weights
        // 2^l in u64 (<=2^38), hi/lo-split REDUX, u64 recombine, one shift.
        // Then per-idx division: lane i owns LUT index i.
        if (tid < 32) {
            int idx = (bmaxpe >> 5) + 1 + lane;      // window [top-15 .. top]
            unsigned long long t = (lane < 16)
                ? ((unsigned long long)(unsigned)s_acc[idx]) << lane : 0ULL;
            unsigned slo = __reduce_add_sync(0xffffffffu, (unsigned)(t & 0xFFFFu));
            unsigned shi = __reduce_add_sync(0xffffffffu, (unsigned)(t >> 16));
            unsigned accv = (unsigned)(((((unsigned long long)shi) << 16) + slo) >> 15);
            // IEEE f32 divide + floorf replicates the reference's float path
            // (accv < 2^24 exact in f32). moi in [0,31].
            int moi = (int)floorf((float)(lutreg << 8) / (float)accv);
            int cl2 = (moi <= 1) ? 0 : (32 - __clz(moi - 1));
            int s7  = 7 - cl2;
            int mu  = min(127, moi << s7);   // reference's clipped mantissa
            s_ms7[lane] = (s7 << 8) | mu;
        }
        __syncthreads();                     // bar3

        // Build 512-entry result table: entry j=(e'<<5)|idx = re-quantized
        // output.  Exact closed form (R3-proven, incl. pow2 128->127 clip and
        // e2=-8 underflow with rne ties-to-even):
        //   d = e' + (3-bmax) - s7;  r = rne(mu*2^min(0,d)) * 2^(max(0,d)-15)
        // Thread tid writes j=tid (e'=warp) and j=tid+256 (e'=warp+8): same
        // lane -> same (s7,mu); hoist unpack + I2F.
        {
            int   w   = s_ms7[lane];         // conflict-free, lane-indexed
            float muf = (float)(w & 255);
            int d = warp + (11 - (bmaxpe >> 5)) - (w >> 8);   // entry 0
            #pragma unroll
            for (int jj = 0; jj < 2; jj++) {
                int dn = min(d, 0);
                int dp = d - dn;
                float m2 = rintf(muf * __int_as_float((dn + 127) << 23));
                s_res[tid + jj * 256] = m2 * __int_as_float((dp + 112) << 23);
                d += 8;                      // entry 1: e' += 8
            }
        }
        __syncthreads();                     // bar4

        // Epilogue: one shared load per element, then store.
        float* orow = out + (size_t)row * D_DIM + tid * EPT;
        float r[EPT];
        #pragma unroll
        for (int k = 0; k < EPT; k++) r[k] = s_res[pe8[k]];
        *(float4*)(orow)     = make_float4(r[0], r[1], r[2], r[3]);
        *(float4*)(orow + 4) = make_float4(r[4], r[5], r[6], r[7]);

        if (!more) break;
        row = nrow; a0 = b0; a1 = b1;
    }
}

extern "C" void kernel_launch(void* const* d_in, const int* in_sizes, int n_in,
                              void* d_out, int out_size)
{
    const float* x = (const float*)d_in[0];
    float* out = (float*)d_out;
    int rows = in_sizes[0] / D_DIM;
    int grid = rows < PGRID ? rows : PGRID;
    mxint_softmax_kernel<<<grid, TPB>>>(x, out, rows);
}